// round 5
// baseline (speedup 1.0000x reference)
#include <cuda_runtime.h>
#include <cstdint>

// Upsampling_68882685493276: 2x nearest-neighbor upsample, fp32
// in : [16, 64, 256, 256]  -> out: [16, 64, 512, 512]
//
// R5 = R2/R3/R4 resubmit (none ran: GPU acquisition timeouts, infra-side).
//
// Strategy: keep LDG.128 reads (reads are only 20% of bytes), but route
// the 1 GiB of stores through the async-proxy bulk path
// (SMEM -> L2 via cp.async.bulk.global.shared::cta), bypassing the
// L1tex store wavefront bottleneck seen in R1 (l1tex=82.1% > dram=72.9%).
//
// Tiling: one tile = 4 input rows (global rows 4t..4t+3).
//   input  slice: float4 [256*t, 256*t + 256)      (4 KiB)
//   output slice: float4 [1024*t, 1024*t + 1024)   (16 KiB, CONTIGUOUS)
// because input row R maps exactly to output float4 range [256R, 256R+256).
// Double-buffered SMEM (2 x 16 KiB), bulk_group commit/wait pipeline.

#define NTHREADS   256
#define TILE_IN4   256            // float4 per tile input (4 rows * 64)
#define TILE_OUT4  1024           // float4 per tile output
#define TILE_OUT_BYTES (TILE_OUT4 * 16)   // 16384

__global__ __launch_bounds__(NTHREADS)
void upsample2x_bulk(const float4* __restrict__ in,
                     float4* __restrict__ out,
                     int ntiles)
{
    __shared__ __align__(128) float4 sbuf[2][TILE_OUT4];   // 32 KiB

    const int tid = threadIdx.x;
    int local = 0;

    for (int t = blockIdx.x; t < ntiles; t += gridDim.x, local++) {
        // Ensure the bulk store that last used this buffer (iter local-2)
        // has drained. With <=2 outstanding groups, wait_group 1 suffices.
        if (tid == 0)
            asm volatile("cp.async.bulk.wait_group 1;" ::: "memory");
        __syncthreads();

        float4* sb = sbuf[local & 1];

        // Load one input float4 per thread, expand 2x2, stage in SMEM.
        float4 v = __ldcs(in + (size_t)t * TILE_IN4 + tid);

        int lr = tid >> 6;        // local input row 0..3
        int w4 = tid & 63;        // input float4 column

        float4 lo = make_float4(v.x, v.x, v.y, v.y);
        float4 hi = make_float4(v.z, v.z, v.w, v.w);

        int b = lr * 256 + 2 * w4;    // two output rows of 128 float4 per lr
        sb[b]       = lo;
        sb[b + 1]   = hi;
        sb[b + 128] = lo;
        sb[b + 129] = hi;

        __syncthreads();

        if (tid == 0) {
            // Make generic STS visible to the async proxy, then bulk-store.
            asm volatile("fence.proxy.async.shared::cta;" ::: "memory");
            uint32_t saddr = (uint32_t)__cvta_generic_to_shared(sb);
            const float4* gdst = out + (size_t)t * TILE_OUT4;
            int nbytes = TILE_OUT_BYTES;
            asm volatile(
                "cp.async.bulk.global.shared::cta.bulk_group [%0], [%1], %2;"
                :: "l"(gdst), "r"(saddr), "r"(nbytes) : "memory");
            asm volatile("cp.async.bulk.commit_group;" ::: "memory");
        }
    }

    // Drain all outstanding bulk stores before CTA exit.
    if (tid == 0)
        asm volatile("cp.async.bulk.wait_group 0;" ::: "memory");
}

extern "C" void kernel_launch(void* const* d_in, const int* in_sizes, int n_in,
                              void* d_out, int out_size)
{
    const float4* in  = (const float4*)d_in[0];
    float4*       out = (float4*)d_out;

    int n4     = in_sizes[0] / 4;        // 16,777,216 input float4
    int ntiles = n4 / TILE_IN4;          // 65,536 tiles

    int blocks = 1184;                   // 148 SMs * 8 CTAs (32 KiB smem each)
    if (blocks > ntiles) blocks = ntiles;

    upsample2x_bulk<<<blocks, NTHREADS>>>(in, out, ntiles);
}

// round 6
// speedup vs baseline: 1.2169x; 1.2169x over previous
#include <cuda_runtime.h>

// Upsampling_68882685493276: 2x nearest-neighbor upsample, fp32
// in : [16, 64, 256, 256] -> out: [16, 64, 512, 512]
//
// R6: back to direct stores (bulk-store path regressed, R5), but fix the
// store sector smear diagnosed from R1: there, each warp STG.128 wrote
// 16B/thread at 32B stride (half-covered sectors, 2x store wavefronts,
// l1tex=82%). Here each thread loads ONE float2 (warp: 256B contiguous),
// expands (a,b)->(a,a,b,b), and stores ONE float4 per output row with
// consecutive addresses across the warp: every STG.128 is a fully
// contiguous 512B / 16 full sectors.
//
// Index math: idx over input float2s [BC=1024][h=256][i=128].
//   out float4 index for row 2h:  o = bc*65536 + h*256 + i = 2*idx - i
//   row 2h+1: o + 128

__global__ __launch_bounds__(256)
void upsample2x_f2(const float2* __restrict__ in,
                   float4* __restrict__ out,
                   int n2)
{
    int idx = blockIdx.x * blockDim.x + threadIdx.x;
    if (idx >= n2) return;

    float2 v = __ldcs(in + idx);
    float4 e = make_float4(v.x, v.x, v.y, v.y);

    int i = idx & 127;          // float2 column within input row
    int o = 2 * idx - i;        // output float4 index, row 2h

    __stcs(out + o,       e);   // row 2h   — warp-contiguous 512B
    __stcs(out + o + 128, e);   // row 2h+1 — warp-contiguous 512B
}

extern "C" void kernel_launch(void* const* d_in, const int* in_sizes, int n_in,
                              void* d_out, int out_size)
{
    const float2* in  = (const float2*)d_in[0];
    float4*       out = (float4*)d_out;

    int n2 = in_sizes[0] / 2;            // 33,554,432 input float2
    int threads = 256;
    int blocks  = (n2 + threads - 1) / threads;   // 131,072

    upsample2x_f2<<<blocks, threads>>>(in, out, n2);
}